// round 15
// baseline (speedup 1.0000x reference)
#include <cuda_runtime.h>
#include <cuda_bf16.h>

// Matcher: final_cost = -2 * gious (class_mat in reference is dead code).
// Per batch b: exact rectangular LSA (row-greedy init with v=0 — rectangular
// duals require v!=0 only on matched columns; column reduction invalid for
// n<m) -> augmenting row reduction (ARR, budget-capped) -> exact Dijkstra.
// Duals stay feasible with slack-0 assignments in every phase, so the result
// is the exact optimum; optimum is unique w.p. 1 for continuous random costs,
// hence identical to the scipy-style reference.
// Outputs (concatenated float32):
//   out[0     .. B*Q)  = per_prop_gt_inds
//   out[B*Q .. 2*B*Q)  = proposal_matched_mask

#define BB 64
#define QQ 256
#define GG 64
#define CPAD 257   // padded cost row stride (floats)

__device__ __forceinline__ unsigned redux_min_u32(unsigned x) {
    unsigned r;
    asm volatile("redux.sync.min.u32 %0, %1, 0xffffffff;" : "=r"(r) : "r"(x));
    return r;
}
// monotonic float <-> u32 order-preserving key
__device__ __forceinline__ unsigned f2k(float f) {
    unsigned x = __float_as_uint(f);
    return (x & 0x80000000u) ? ~x : (x | 0x80000000u);
}
__device__ __forceinline__ float k2f(unsigned k) {
    unsigned x = (k & 0x80000000u) ? (k ^ 0x80000000u) : ~k;
    return __uint_as_float(x);
}

__global__ void __launch_bounds__(32, 1) matcher_lsa_kernel(
    const float* __restrict__ gious,   // [B, Q, G] float32
    const int*   __restrict__ nactRaw, // int32 view of nactual_gt
    float*       __restrict__ out)     // [2*B*Q] float32
{
    extern __shared__ char smem_raw[];
    float* cost    = (float*)smem_raw;            // GG * CPAD
    float* shsh    = cost + GG * CPAD;            // QQ shortest mirror
    float* u       = shsh + QQ;                   // GG
    int*   path    = (int*)(u + GG);              // QQ
    int*   row4col = path + QQ;                   // QQ
    int*   col4row = row4col + QQ;                // GG
    int*   claim   = col4row + GG;                // QQ greedy claims
    int*   rmArg   = claim + QQ;                  // GG row argmins

    const int b    = blockIdx.x;
    const int lane = threadIdx.x;
    const float FINF = __uint_as_float(0x7f800000u);
    const unsigned FULL = 0xffffffffu;

    // nactual_gt dtype detection (values >= 1, int64 -> odd 32-bit words are 0)
    int n;
    {
        bool is64 = (nactRaw[1] == 0);
        n = is64 ? nactRaw[2 * b] : nactRaw[b];
        if (n > GG) n = GG;
        if (n < 0)  n = 0;
    }

    // ---- init small state
    float vv[8];      // dual v for own columns q = lane + 32k
    float sh[8];      // shortest for own columns
    unsigned cpack[8];// (q<<9)|(row4col[q]+1) mirror for own columns
#pragma unroll
    for (int k = 0; k < 8; k++) {
        vv[k] = 0.0f;
        row4col[lane + 32 * k] = -1;
        claim[lane + 32 * k]   = 0x7fffffff;
    }
    col4row[lane] = -1;  col4row[lane + 32] = -1;

    // ---- stage cost tile (cost[g][q] = -2*gious[b,q,g]) with fused row-min.
    {
        const float4* gb4 = (const float4*)(gious + (size_t)b * QQ * GG);
        const int g0 = (lane & 15) << 2;
        float m0 = FINF, m1 = FINF, m2 = FINF, m3 = FINF;
        int   a0 = 0,    a1 = 0,    a2 = 0,    a3 = 0;
        for (int t = lane; t < (QQ * GG) / 4; t += 32) {
            float4 val = gb4[t];
            const int q = t >> 4;
            const float c0 = -2.0f * val.x, c1 = -2.0f * val.y;
            const float c2 = -2.0f * val.z, c3 = -2.0f * val.w;
            cost[(g0 + 0) * CPAD + q] = c0;
            cost[(g0 + 1) * CPAD + q] = c1;
            cost[(g0 + 2) * CPAD + q] = c2;
            cost[(g0 + 3) * CPAD + q] = c3;
            if (c0 < m0) { m0 = c0; a0 = q; }
            if (c1 < m1) { m1 = c1; a1 = q; }
            if (c2 < m2) { m2 = c2; a2 = q; }
            if (c3 < m3) { m3 = c3; a3 = q; }
        }
#define MERGE16(m, a) { \
            float om = __shfl_xor_sync(FULL, m, 16); \
            int   oa = __shfl_xor_sync(FULL, a, 16); \
            if (om < m || (om == m && oa < a)) { m = om; a = oa; } }
        MERGE16(m0, a0) MERGE16(m1, a1) MERGE16(m2, a2) MERGE16(m3, a3)
#undef MERGE16
        if (lane < 16) {
            u[g0 + 0] = m0; rmArg[g0 + 0] = a0;
            u[g0 + 1] = m1; rmArg[g0 + 1] = a1;
            u[g0 + 2] = m2; rmArg[g0 + 2] = a2;
            u[g0 + 3] = m3; rmArg[g0 + 3] = a3;
        }
    }
    __syncwarp();

    // ---- parallel greedy assignment: lowest row wins each claimed column
    const int rm0 = rmArg[lane], rm1 = rmArg[lane + 32];
    if (lane < n)      atomicMin(&claim[rm0], lane);
    if (lane + 32 < n) atomicMin(&claim[rm1], lane + 32);
    __syncwarp();
    bool g_a0 = (lane < n)      && (claim[rm0] == lane);
    bool g_a1 = (lane + 32 < n) && (claim[rm1] == lane + 32);
    if (g_a0) { col4row[lane]      = rm0; row4col[rm0] = lane; }
    if (g_a1) { col4row[lane + 32] = rm1; row4col[rm1] = lane + 32; }
    unsigned bal0 = __ballot_sync(FULL, g_a0);
    unsigned bal1 = __ballot_sync(FULL, g_a1);
    const unsigned long long nmask = (n >= 64) ? ~0ull : ((1ull << n) - 1ull);
    unsigned long long free_rows =
        ~(((unsigned long long)bal1 << 32) | (unsigned long long)bal0) & nmask;
    __syncwarp();
#pragma unroll
    for (int k = 0; k < 8; k++)
        cpack[k] = ((unsigned)(lane + 32 * k) << 9)
                 | (unsigned)(row4col[lane + 32 * k] + 1);

    // merged (value, pack) pair selection: ties pick first operand (lower q)
#define PMERGE(va, pa, vb, pb, vo, po) { \
        po = (va <= vb) ? pa : pb; vo = fminf(va, vb); }

    // ---- augmenting row reduction (JV): tighten duals, steal columns.
    unsigned long long dij = 0;
    {
        unsigned long long work = free_rows;
        int budget = 96;
        while (work) {
            int i = __ffsll((long long)work) - 1;
            work &= work - 1;
            bool active = true;
            while (active) {
                if (--budget < 0) { dij |= (1ull << i) | work; work = 0; break; }
                const float* crow = cost + i * CPAD;
                float rq[8];
#pragma unroll
                for (int k = 0; k < 8; k++) rq[k] = crow[lane + 32 * k] - vv[k];

                // merged (lo, hi, pack) triple tree: lo=min, hi=2nd-min,
                // pack = pack of lowest-q argmin
                float l01, l23, l45, l67, lA, lB, m, s;
                unsigned p01, p23, p45, p67, pA, pB, pkl;
                PMERGE(rq[0], cpack[0], rq[1], cpack[1], l01, p01)
                PMERGE(rq[2], cpack[2], rq[3], cpack[3], l23, p23)
                PMERGE(rq[4], cpack[4], rq[5], cpack[5], l45, p45)
                PMERGE(rq[6], cpack[6], rq[7], cpack[7], l67, p67)
                float h01 = fmaxf(rq[0], rq[1]), h23 = fmaxf(rq[2], rq[3]);
                float h45 = fmaxf(rq[4], rq[5]), h67 = fmaxf(rq[6], rq[7]);
                PMERGE(l01, p01, l23, p23, lA, pA)
                float hA = fminf(fmaxf(l01, l23), fminf(h01, h23));
                PMERGE(l45, p45, l67, p67, lB, pB)
                float hB = fminf(fmaxf(l45, l67), fminf(h45, h67));
                PMERGE(lA, pA, lB, pB, m, pkl)
                s = fminf(fmaxf(lA, lB), fminf(hA, hB));

                const unsigned km = f2k(m);
                const unsigned g1 = redux_min_u32(km);
                const float    u1 = k2f(g1);
                const bool     win = (km == g1);

                // two overlapped reduxes: winners' packs + 2nd-min
                const unsigned pk2 = win ? pkl : 0xFFFFFFFFu;
                const unsigned c2  = win ? f2k(s) : km;
                const unsigned packed = redux_min_u32(pk2);
                const unsigned g2     = redux_min_u32(c2);
                const unsigned nb = __ballot_sync(FULL, win);
                const float u2 = (__popc(nb) >= 2) ? u1 : k2f(g2);

                const int j1 = (int)(packed >> 9);
                const int k1 = (int)(packed & 511u) - 1;

                if (lane == 0) u[i] = u2;

                if (u1 < u2) {                // take j1 (steal if held)
                    if ((j1 & 31) == lane) {
                        vv[j1 >> 5] -= (u2 - u1);
                        cpack[j1 >> 5] = ((unsigned)j1 << 9) | (unsigned)(i + 1);
                    }
                    if (lane == 0) {
                        row4col[j1] = i; col4row[i] = j1;
                        if (k1 >= 0) col4row[k1] = -1;
                    }
                    if (k1 >= 0) i = k1;       // continue with displaced row
                    else         active = false;
                } else {                       // u1 == u2 (>=2 cols at u1)
                    if (k1 < 0) {              // j1 free: take it (slack 0)
                        if ((j1 & 31) == lane)
                            cpack[j1 >> 5] = ((unsigned)j1 << 9) | (unsigned)(i + 1);
                        if (lane == 0) { row4col[j1] = i; col4row[i] = j1; }
                        active = false;
                    } else {
                        // j2 = next col with rq == u2, excluding j1 (rare)
                        unsigned pkx = 0xFFFFFFFFu;
#pragma unroll
                        for (int k = 0; k < 8; k++) {
                            const int q = lane + 32 * k;
                            const bool ok = (q != j1) && (rq[k] == u2);
                            pkx = min(pkx, ok ? cpack[k] : 0xFFFFFFFFu);
                        }
                        const unsigned packed2 = redux_min_u32(pkx);
                        const int j2  = (int)(packed2 >> 9);
                        const int k2r = (int)(packed2 & 511u) - 1;
                        if (k2r < 0) {         // j2 free: take it (slack 0)
                            if ((j2 & 31) == lane)
                                cpack[j2 >> 5] = ((unsigned)j2 << 9) | (unsigned)(i + 1);
                            if (lane == 0) { row4col[j2] = i; col4row[i] = j2; }
                        } else {
                            dij |= 1ull << i;  // defer to Dijkstra
                        }
                        active = false;
                    }
                }
            }
        }
    }
    __syncwarp();

    // ---- exact Dijkstra augmentation for remaining rows
    while (dij) {
        const int cur_row = __ffsll((long long)dij) - 1;
        dij &= dij - 1;

        // skip rows already matched by ARR before budget ran out
        if (col4row[cur_row] >= 0) continue;

        unsigned scanned = 0;          // bit k -> own column lane+32k in SC
        unsigned long long sr = 0;     // scanned-row set (uniform)
#pragma unroll
        for (int k = 0; k < 8; k++) sh[k] = FINF;

        int   i      = cur_row;
        float minval = 0.0f;
        int   sink;

        while (true) {
            sr |= 1ull << i;
            const float base = minval - u[i];
            const float* crow = cost + i * CPAD;

            float bb[8];
#pragma unroll
            for (int k = 0; k < 8; k++) bb[k] = base - vv[k];

            float cand[8];
#pragma unroll
            for (int k = 0; k < 8; k++) {
                const int q = lane + 32 * k;
                const bool un = !((scanned >> k) & 1u);
                const float r = crow[q] + bb[k];
                if (un && r < sh[k]) { sh[k] = r; path[q] = i; }
                cand[k] = un ? sh[k] : FINF;
            }

            // merged (value, pack) tree -> (bv, pkl), ties pick lowest q
            float l01, l23, l45, l67, lA, lB, bv;
            unsigned p01, p23, p45, p67, pA, pB, pkl;
            PMERGE(cand[0], cpack[0], cand[1], cpack[1], l01, p01)
            PMERGE(cand[2], cpack[2], cand[3], cpack[3], l23, p23)
            PMERGE(cand[4], cpack[4], cand[5], cpack[5], l45, p45)
            PMERGE(cand[6], cpack[6], cand[7], cpack[7], l67, p67)
            PMERGE(l01, p01, l23, p23, lA, pA)
            PMERGE(l45, p45, l67, p67, lB, pB)
            PMERGE(lA, pA, lB, pB, bv, pkl)

            const unsigned km   = f2k(bv);
            const unsigned gkey = redux_min_u32(km);
            const unsigned pk2  = (km == gkey) ? pkl : 0xFFFFFFFFu;
            const unsigned packed = redux_min_u32(pk2);
            minval = k2f(gkey);

            const int j  = (int)(packed >> 9);
            const int r4 = (int)(packed & 511u) - 1;
            if ((j & 31) == lane) scanned |= 1u << (j >> 5);
            if (r4 < 0) { sink = j; break; }
            i = r4;
        }

        // write back shortest for scanned columns (dual u update reads them)
#pragma unroll
        for (int k = 0; k < 8; k++)
            if ((scanned >> k) & 1u) shsh[lane + 32 * k] = sh[k];
        __syncwarp();

        // dual updates
#pragma unroll
        for (int h = 0; h < 2; h++) {
            const int r = lane + 32 * h;
            if (((sr >> r) & 1ull) && r != cur_row) {
                u[r] += minval - shsh[col4row[r]];
            }
        }
        if (lane == 0) u[cur_row] += minval;
#pragma unroll
        for (int k = 0; k < 8; k++) {
            if ((scanned >> k) & 1u) vv[k] -= minval - sh[k];
        }
        __syncwarp();

        // augment along alternating path (serial, lane 0)
        if (lane == 0) {
            int j = sink;
            while (true) {
                int ii = path[j];
                row4col[j] = ii;
                int t = col4row[ii];
                col4row[ii] = j;
                j = t;
                if (ii == cur_row) break;
            }
        }
        __syncwarp();
        // refresh cpack mirrors (row4col changed along the augmenting path)
#pragma unroll
        for (int k = 0; k < 8; k++)
            cpack[k] = ((unsigned)(lane + 32 * k) << 9)
                     | (unsigned)(row4col[lane + 32 * k] + 1);
    }
#undef PMERGE

    // ---- outputs
    float* out_ind  = out + (size_t)b * QQ;
    float* out_mask = out + (size_t)BB * QQ + (size_t)b * QQ;
#pragma unroll
    for (int k = 0; k < 8; k++) {
        const int q = lane + 32 * k;
        const int r = row4col[q];
        out_ind[q]  = (r >= 0) ? (float)r : 0.0f;
        out_mask[q] = (r >= 0) ? 1.0f : 0.0f;
    }
}

extern "C" void kernel_launch(void* const* d_in, const int* in_sizes, int n_in,
                              void* d_out, int out_size) {
    const float* gious = nullptr;
    const int*   nact  = nullptr;
    for (int i = 0; i < n_in; i++) {
        if (in_sizes[i] == BB * QQ * GG)      gious = (const float*)d_in[i];
        else if (in_sizes[i] == BB)           nact  = (const int*)d_in[i];
    }

    const size_t smem = (size_t)GG * CPAD * sizeof(float)   // cost
                      + (size_t)QQ * sizeof(float)          // shortest mirror
                      + (size_t)GG * sizeof(float)          // u
                      + (size_t)QQ * sizeof(int)            // path
                      + (size_t)QQ * sizeof(int)            // row4col
                      + (size_t)GG * sizeof(int)            // col4row
                      + (size_t)QQ * sizeof(int)            // claim
                      + (size_t)GG * sizeof(int);           // row argmin

    cudaFuncSetAttribute(matcher_lsa_kernel,
                         cudaFuncAttributeMaxDynamicSharedMemorySize, (int)smem);

    matcher_lsa_kernel<<<BB, 32, smem>>>(gious, nact, (float*)d_out);
}

// round 16
// speedup vs baseline: 1.3069x; 1.3069x over previous
#include <cuda_runtime.h>
#include <cuda_bf16.h>

// Matcher: final_cost = -2 * gious (class_mat in reference is dead code).
// Per batch b: exact rectangular LSA (row-greedy init with v=0 — rectangular
// duals require v!=0 only on matched columns; column reduction invalid for
// n<m) -> augmenting row reduction (ARR, budget-capped) -> exact Dijkstra.
// Duals stay feasible with slack-0 assignments in every phase, so the result
// is the exact optimum; optimum is unique w.p. 1 for continuous random costs,
// hence identical to the scipy-style reference.
// Outputs (concatenated float32):
//   out[0     .. B*Q)  = per_prop_gt_inds
//   out[B*Q .. 2*B*Q)  = proposal_matched_mask

#define BB 64
#define QQ 256
#define GG 64
#define CPAD 257   // padded cost row stride (floats)

__device__ __forceinline__ unsigned redux_min_u32(unsigned x) {
    unsigned r;
    asm volatile("redux.sync.min.u32 %0, %1, 0xffffffff;" : "=r"(r) : "r"(x));
    return r;
}
// monotonic float <-> u32 order-preserving key
__device__ __forceinline__ unsigned f2k(float f) {
    unsigned x = __float_as_uint(f);
    return (x & 0x80000000u) ? ~x : (x | 0x80000000u);
}
__device__ __forceinline__ float k2f(unsigned k) {
    unsigned x = (k & 0x80000000u) ? (k ^ 0x80000000u) : ~k;
    return __uint_as_float(x);
}

__global__ void __launch_bounds__(32, 1) matcher_lsa_kernel(
    const float* __restrict__ gious,   // [B, Q, G] float32
    const int*   __restrict__ nactRaw, // int32 view of nactual_gt
    float*       __restrict__ out)     // [2*B*Q] float32
{
    extern __shared__ char smem_raw[];
    float* cost    = (float*)smem_raw;            // GG * CPAD
    float* shsh    = cost + GG * CPAD;            // QQ shortest mirror
    float* u       = shsh + QQ;                   // GG
    int*   path    = (int*)(u + GG);              // QQ
    int*   row4col = path + QQ;                   // QQ
    int*   col4row = row4col + QQ;                // GG
    int*   claim   = col4row + GG;                // QQ greedy claims
    int*   rmArg   = claim + QQ;                  // GG row argmins

    const int b    = blockIdx.x;
    const int lane = threadIdx.x;
    const float FINF = __uint_as_float(0x7f800000u);
    const unsigned FULL = 0xffffffffu;

    // nactual_gt dtype detection (values >= 1, int64 -> odd 32-bit words are 0)
    int n;
    {
        bool is64 = (nactRaw[1] == 0);
        n = is64 ? nactRaw[2 * b] : nactRaw[b];
        if (n > GG) n = GG;
        if (n < 0)  n = 0;
    }

    // ---- init small state
    float vv[8];   // dual v for own columns q = lane + 32k
    float sh[8];   // shortest for own columns (FINF once scanned; real value
    int   r4c[8];  // lives in shsh from scan time on)
#pragma unroll
    for (int k = 0; k < 8; k++) {
        vv[k] = 0.0f;
        row4col[lane + 32 * k] = -1;
        claim[lane + 32 * k]   = 0x7fffffff;
    }
    col4row[lane] = -1;  col4row[lane + 32] = -1;

    // ---- stage cost tile (cost[g][q] = -2*gious[b,q,g]) with fused row-min.
    {
        const float4* gb4 = (const float4*)(gious + (size_t)b * QQ * GG);
        const int g0 = (lane & 15) << 2;
        float m0 = FINF, m1 = FINF, m2 = FINF, m3 = FINF;
        int   a0 = 0,    a1 = 0,    a2 = 0,    a3 = 0;
        for (int t = lane; t < (QQ * GG) / 4; t += 32) {
            float4 val = gb4[t];
            const int q = t >> 4;
            const float c0 = -2.0f * val.x, c1 = -2.0f * val.y;
            const float c2 = -2.0f * val.z, c3 = -2.0f * val.w;
            cost[(g0 + 0) * CPAD + q] = c0;
            cost[(g0 + 1) * CPAD + q] = c1;
            cost[(g0 + 2) * CPAD + q] = c2;
            cost[(g0 + 3) * CPAD + q] = c3;
            if (c0 < m0) { m0 = c0; a0 = q; }
            if (c1 < m1) { m1 = c1; a1 = q; }
            if (c2 < m2) { m2 = c2; a2 = q; }
            if (c3 < m3) { m3 = c3; a3 = q; }
        }
#define MERGE16(m, a) { \
            float om = __shfl_xor_sync(FULL, m, 16); \
            int   oa = __shfl_xor_sync(FULL, a, 16); \
            if (om < m || (om == m && oa < a)) { m = om; a = oa; } }
        MERGE16(m0, a0) MERGE16(m1, a1) MERGE16(m2, a2) MERGE16(m3, a3)
#undef MERGE16
        if (lane < 16) {
            u[g0 + 0] = m0; rmArg[g0 + 0] = a0;
            u[g0 + 1] = m1; rmArg[g0 + 1] = a1;
            u[g0 + 2] = m2; rmArg[g0 + 2] = a2;
            u[g0 + 3] = m3; rmArg[g0 + 3] = a3;
        }
    }
    __syncwarp();

    // ---- parallel greedy assignment: lowest row wins each claimed column
    const int rm0 = rmArg[lane], rm1 = rmArg[lane + 32];
    if (lane < n)      atomicMin(&claim[rm0], lane);
    if (lane + 32 < n) atomicMin(&claim[rm1], lane + 32);
    __syncwarp();
    bool g_a0 = (lane < n)      && (claim[rm0] == lane);
    bool g_a1 = (lane + 32 < n) && (claim[rm1] == lane + 32);
    if (g_a0) { col4row[lane]      = rm0; row4col[rm0] = lane; }
    if (g_a1) { col4row[lane + 32] = rm1; row4col[rm1] = lane + 32; }
    unsigned bal0 = __ballot_sync(FULL, g_a0);
    unsigned bal1 = __ballot_sync(FULL, g_a1);
    const unsigned long long nmask = (n >= 64) ? ~0ull : ((1ull << n) - 1ull);
    unsigned long long free_rows =
        ~(((unsigned long long)bal1 << 32) | (unsigned long long)bal0) & nmask;
    __syncwarp();
#pragma unroll
    for (int k = 0; k < 8; k++) r4c[k] = row4col[lane + 32 * k];

    // ---- augmenting row reduction (JV): tighten duals, steal columns.
    unsigned long long dij = 0;
    {
        unsigned long long work = free_rows;
        int budget = 96;
        while (work) {
            int i = __ffsll((long long)work) - 1;
            work &= work - 1;
            bool active = true;
            while (active) {
                if (--budget < 0) { dij |= (1ull << i) | work; work = 0; break; }
                const float* crow = cost + i * CPAD;
                float rq[8];
#pragma unroll
                for (int k = 0; k < 8; k++) rq[k] = crow[lane + 32 * k] - vv[k];

                // lane-local (min m, 2nd-min s) via pairwise merge tree
                float lo01 = fminf(rq[0], rq[1]), hi01 = fmaxf(rq[0], rq[1]);
                float lo23 = fminf(rq[2], rq[3]), hi23 = fmaxf(rq[2], rq[3]);
                float lo45 = fminf(rq[4], rq[5]), hi45 = fmaxf(rq[4], rq[5]);
                float lo67 = fminf(rq[6], rq[7]), hi67 = fmaxf(rq[6], rq[7]);
                float loA = fminf(lo01, lo23);
                float sA  = fminf(fmaxf(lo01, lo23), fminf(hi01, hi23));
                float loB = fminf(lo45, lo67);
                float sB  = fminf(fmaxf(lo45, lo67), fminf(hi45, hi67));
                float m   = fminf(loA, loB);
                float s   = fminf(fmaxf(loA, loB), fminf(sA, sB));

                // lane-local argmin pack vs OWN min (ready before redux1)
                unsigned pkl = 0xFFFFFFFFu;
#pragma unroll
                for (int k = 0; k < 8; k++) {
                    const unsigned c = ((unsigned)(lane + 32 * k) << 9)
                                     | (unsigned)(r4c[k] + 1);
                    pkl = min(pkl, (rq[k] == m) ? c : 0xFFFFFFFFu);
                }

                const unsigned km = f2k(m);
                const unsigned g1 = redux_min_u32(km);
                const float    u1 = k2f(g1);
                const bool     win = (km == g1);

                // two overlapped reduxes: winners' packs + 2nd-min
                const unsigned pk2 = win ? pkl : 0xFFFFFFFFu;
                const unsigned c2  = win ? f2k(s) : km;
                const unsigned packed = redux_min_u32(pk2);
                const unsigned g2     = redux_min_u32(c2);
                const unsigned nb = __ballot_sync(FULL, win);
                const float u2 = (__popc(nb) >= 2) ? u1 : k2f(g2);

                const int j1 = (int)(packed >> 9);
                const int k1 = (int)(packed & 511u) - 1;

                if (lane == 0) u[i] = u2;

                if (u1 < u2) {                // take j1 (steal if held)
                    if ((j1 & 31) == lane) { vv[j1 >> 5] -= (u2 - u1); r4c[j1 >> 5] = i; }
                    if (lane == 0) {
                        row4col[j1] = i; col4row[i] = j1;
                        if (k1 >= 0) col4row[k1] = -1;
                    }
                    if (k1 >= 0) i = k1;       // continue with displaced row
                    else         active = false;
                } else {                       // u1 == u2 (>=2 cols at u1)
                    if (k1 < 0) {              // j1 free: take it (slack 0)
                        if ((j1 & 31) == lane) r4c[j1 >> 5] = i;
                        if (lane == 0) { row4col[j1] = i; col4row[i] = j1; }
                        active = false;
                    } else {
                        // j2 = next col with rq == u2, excluding j1 (rare)
                        unsigned pkx = 0xFFFFFFFFu;
#pragma unroll
                        for (int k = 0; k < 8; k++) {
                            const int q = lane + 32 * k;
                            const unsigned c = ((unsigned)q << 9)
                                             | (unsigned)(r4c[k] + 1);
                            const bool ok = (q != j1) && (rq[k] == u2);
                            pkx = min(pkx, ok ? c : 0xFFFFFFFFu);
                        }
                        const unsigned packed2 = redux_min_u32(pkx);
                        const int j2  = (int)(packed2 >> 9);
                        const int k2r = (int)(packed2 & 511u) - 1;
                        if (k2r < 0) {         // j2 free: take it (slack 0)
                            if ((j2 & 31) == lane) r4c[j2 >> 5] = i;
                            if (lane == 0) { row4col[j2] = i; col4row[i] = j2; }
                        } else {
                            dij |= 1ull << i;  // defer to Dijkstra
                        }
                        active = false;
                    }
                }
            }
        }
    }
    __syncwarp();

    // ---- exact Dijkstra augmentation for remaining rows
    while (dij) {
        const int cur_row = __ffsll((long long)dij) - 1;
        dij &= dij - 1;

        // skip rows already matched by ARR before budget ran out
        if (col4row[cur_row] >= 0) continue;

        unsigned scanned = 0;          // bit k -> own column lane+32k in SC
        unsigned long long sr = 0;     // scanned-row set (uniform)
#pragma unroll
        for (int k = 0; k < 8; k++) sh[k] = FINF;

        int   i      = cur_row;
        float minval = 0.0f;
        int   sink;

        while (true) {
            sr |= 1ull << i;
            const float base = minval - u[i];
            const float* crow = cost + i * CPAD;

            float bb[8];
#pragma unroll
            for (int k = 0; k < 8; k++) bb[k] = base - vv[k];

            // relax; invariant: sh[k] == FINF for scanned columns, so cand
            // IS sh (no select). un-guard still protects sh/path overwrite.
#pragma unroll
            for (int k = 0; k < 8; k++) {
                const int q = lane + 32 * k;
                const bool un = !((scanned >> k) & 1u);
                const float r = crow[q] + bb[k];
                if (un && r < sh[k]) { sh[k] = r; path[q] = i; }
            }
            float m01 = fminf(sh[0], sh[1]), m23 = fminf(sh[2], sh[3]);
            float m45 = fminf(sh[4], sh[5]), m67 = fminf(sh[6], sh[7]);
            float bv  = fminf(fminf(m01, m23), fminf(m45, m67));

            // lane-local argmin pack vs OWN min (ready before redux1)
            unsigned pkl = 0xFFFFFFFFu;
#pragma unroll
            for (int k = 0; k < 8; k++) {
                const unsigned c = ((unsigned)(lane + 32 * k) << 9)
                                 | (unsigned)(r4c[k] + 1);
                pkl = min(pkl, (sh[k] == bv) ? c : 0xFFFFFFFFu);
            }

            const unsigned km   = f2k(bv);
            const unsigned gkey = redux_min_u32(km);
            const unsigned pk2  = (km == gkey) ? pkl : 0xFFFFFFFFu;
            const unsigned packed = redux_min_u32(pk2);
            minval = k2f(gkey);

            const int j  = (int)(packed >> 9);
            const int r4 = (int)(packed & 511u) - 1;
            if ((j & 31) == lane) {            // owner: save value, mark, nuke
                const int kk = j >> 5;
                shsh[j] = sh[kk];              // == minval (final shortest[j])
                sh[kk] = FINF;
                scanned |= 1u << kk;
            }
            if (r4 < 0) { sink = j; break; }
            i = r4;
        }
        __syncwarp();   // order shsh writes before cross-lane reads below

        // dual updates (shsh holds shortest for all scanned columns)
#pragma unroll
        for (int h = 0; h < 2; h++) {
            const int r = lane + 32 * h;
            if (((sr >> r) & 1ull) && r != cur_row) {
                u[r] += minval - shsh[col4row[r]];
            }
        }
        if (lane == 0) u[cur_row] += minval;
#pragma unroll
        for (int k = 0; k < 8; k++) {
            if ((scanned >> k) & 1u) vv[k] -= minval - shsh[lane + 32 * k];
        }
        __syncwarp();

        // augment along alternating path (serial, lane 0)
        if (lane == 0) {
            int j = sink;
            while (true) {
                int ii = path[j];
                row4col[j] = ii;
                int t = col4row[ii];
                col4row[ii] = j;
                j = t;
                if (ii == cur_row) break;
            }
        }
        __syncwarp();
#pragma unroll
        for (int k = 0; k < 8; k++) r4c[k] = row4col[lane + 32 * k];
    }

    // ---- outputs
    float* out_ind  = out + (size_t)b * QQ;
    float* out_mask = out + (size_t)BB * QQ + (size_t)b * QQ;
#pragma unroll
    for (int k = 0; k < 8; k++) {
        const int q = lane + 32 * k;
        const int r = row4col[q];
        out_ind[q]  = (r >= 0) ? (float)r : 0.0f;
        out_mask[q] = (r >= 0) ? 1.0f : 0.0f;
    }
}

extern "C" void kernel_launch(void* const* d_in, const int* in_sizes, int n_in,
                              void* d_out, int out_size) {
    const float* gious = nullptr;
    const int*   nact  = nullptr;
    for (int i = 0; i < n_in; i++) {
        if (in_sizes[i] == BB * QQ * GG)      gious = (const float*)d_in[i];
        else if (in_sizes[i] == BB)           nact  = (const int*)d_in[i];
    }

    const size_t smem = (size_t)GG * CPAD * sizeof(float)   // cost
                      + (size_t)QQ * sizeof(float)          // shortest mirror
                      + (size_t)GG * sizeof(float)          // u
                      + (size_t)QQ * sizeof(int)            // path
                      + (size_t)QQ * sizeof(int)            // row4col
                      + (size_t)GG * sizeof(int)            // col4row
                      + (size_t)QQ * sizeof(int)            // claim
                      + (size_t)GG * sizeof(int);           // row argmin

    cudaFuncSetAttribute(matcher_lsa_kernel,
                         cudaFuncAttributeMaxDynamicSharedMemorySize, (int)smem);

    matcher_lsa_kernel<<<BB, 32, smem>>>(gious, nact, (float*)d_out);
}

// round 17
// speedup vs baseline: 1.4484x; 1.1083x over previous
#include <cuda_runtime.h>
#include <cuda_bf16.h>

// Matcher: final_cost = -2 * gious (class_mat in reference is dead code).
// Per batch b: exact rectangular LSA (row-greedy init with v=0 — rectangular
// duals require v!=0 only on matched columns; column reduction invalid for
// n<m) -> augmenting row reduction (ARR) -> exact Dijkstra augmentation.
// Duals stay feasible with slack-0 assignments in every phase, so the result
// is the exact optimum; optimum is unique w.p. 1 for continuous random costs,
// hence identical to the scipy-style reference.
// Outputs (concatenated float32):
//   out[0     .. B*Q)  = per_prop_gt_inds
//   out[B*Q .. 2*B*Q)  = proposal_matched_mask
//
// CONVERGED CHAMPION (R6 structure): FMNMX min-tree + equality pack loop +
// two pipelined redux.sync collectives. Measured alternatives all regressed:
// 8x ballot argmin (+4.1us), ballot+shfl (+0.5us), select-merge trees
// (+8.5us), sh-nuke invariant (+2.1us), CR duals (WRONG for n<m).

#define BB 64
#define QQ 256
#define GG 64
#define CPAD 257   // padded cost row stride (floats)

__device__ __forceinline__ unsigned redux_min_u32(unsigned x) {
    unsigned r;
    asm volatile("redux.sync.min.u32 %0, %1, 0xffffffff;" : "=r"(r) : "r"(x));
    return r;
}
// monotonic float <-> u32 order-preserving key
__device__ __forceinline__ unsigned f2k(float f) {
    unsigned x = __float_as_uint(f);
    return (x & 0x80000000u) ? ~x : (x | 0x80000000u);
}
__device__ __forceinline__ float k2f(unsigned k) {
    unsigned x = (k & 0x80000000u) ? (k ^ 0x80000000u) : ~k;
    return __uint_as_float(x);
}

__global__ void __launch_bounds__(32, 1) matcher_lsa_kernel(
    const float* __restrict__ gious,   // [B, Q, G] float32
    const int*   __restrict__ nactRaw, // int32 view of nactual_gt
    float*       __restrict__ out)     // [2*B*Q] float32
{
    extern __shared__ char smem_raw[];
    float* cost    = (float*)smem_raw;            // GG * CPAD
    float* shsh    = cost + GG * CPAD;            // QQ shortest mirror
    float* u       = shsh + QQ;                   // GG
    int*   path    = (int*)(u + GG);              // QQ
    int*   row4col = path + QQ;                   // QQ
    int*   col4row = row4col + QQ;                // GG
    int*   claim   = col4row + GG;                // QQ greedy claims
    int*   rmArg   = claim + QQ;                  // GG row argmins

    const int b    = blockIdx.x;
    const int lane = threadIdx.x;
    const float FINF = __uint_as_float(0x7f800000u);
    const unsigned FULL = 0xffffffffu;

    // nactual_gt dtype detection (values >= 1, int64 -> odd 32-bit words are 0)
    int n;
    {
        bool is64 = (nactRaw[1] == 0);
        n = is64 ? nactRaw[2 * b] : nactRaw[b];
        if (n > GG) n = GG;
        if (n < 0)  n = 0;
    }

    // ---- init small state
    float vv[8];   // dual v for own columns q = lane + 32k
    float sh[8];   // shortest for own columns
    int   r4c[8];  // register mirror of row4col for own columns
#pragma unroll
    for (int k = 0; k < 8; k++) {
        vv[k] = 0.0f;
        row4col[lane + 32 * k] = -1;
        claim[lane + 32 * k]   = 0x7fffffff;
    }
    col4row[lane] = -1;  col4row[lane + 32] = -1;

    // ---- stage cost tile (cost[g][q] = -2*gious[b,q,g]) with fused row-min.
    {
        const float4* gb4 = (const float4*)(gious + (size_t)b * QQ * GG);
        const int g0 = (lane & 15) << 2;
        float m0 = FINF, m1 = FINF, m2 = FINF, m3 = FINF;
        int   a0 = 0,    a1 = 0,    a2 = 0,    a3 = 0;
        for (int t = lane; t < (QQ * GG) / 4; t += 32) {
            float4 val = gb4[t];
            const int q = t >> 4;
            const float c0 = -2.0f * val.x, c1 = -2.0f * val.y;
            const float c2 = -2.0f * val.z, c3 = -2.0f * val.w;
            cost[(g0 + 0) * CPAD + q] = c0;
            cost[(g0 + 1) * CPAD + q] = c1;
            cost[(g0 + 2) * CPAD + q] = c2;
            cost[(g0 + 3) * CPAD + q] = c3;
            if (c0 < m0) { m0 = c0; a0 = q; }
            if (c1 < m1) { m1 = c1; a1 = q; }
            if (c2 < m2) { m2 = c2; a2 = q; }
            if (c3 < m3) { m3 = c3; a3 = q; }
        }
#define MERGE16(m, a) { \
            float om = __shfl_xor_sync(FULL, m, 16); \
            int   oa = __shfl_xor_sync(FULL, a, 16); \
            if (om < m || (om == m && oa < a)) { m = om; a = oa; } }
        MERGE16(m0, a0) MERGE16(m1, a1) MERGE16(m2, a2) MERGE16(m3, a3)
#undef MERGE16
        if (lane < 16) {
            u[g0 + 0] = m0; rmArg[g0 + 0] = a0;
            u[g0 + 1] = m1; rmArg[g0 + 1] = a1;
            u[g0 + 2] = m2; rmArg[g0 + 2] = a2;
            u[g0 + 3] = m3; rmArg[g0 + 3] = a3;
        }
    }
    __syncwarp();

    // ---- parallel greedy assignment: lowest row wins each claimed column
    const int rm0 = rmArg[lane], rm1 = rmArg[lane + 32];
    if (lane < n)      atomicMin(&claim[rm0], lane);
    if (lane + 32 < n) atomicMin(&claim[rm1], lane + 32);
    __syncwarp();
    bool g_a0 = (lane < n)      && (claim[rm0] == lane);
    bool g_a1 = (lane + 32 < n) && (claim[rm1] == lane + 32);
    if (g_a0) { col4row[lane]      = rm0; row4col[rm0] = lane; }
    if (g_a1) { col4row[lane + 32] = rm1; row4col[rm1] = lane + 32; }
    unsigned bal0 = __ballot_sync(FULL, g_a0);
    unsigned bal1 = __ballot_sync(FULL, g_a1);
    const unsigned long long nmask = (n >= 64) ? ~0ull : ((1ull << n) - 1ull);
    unsigned long long free_rows =
        ~(((unsigned long long)bal1 << 32) | (unsigned long long)bal0) & nmask;
    __syncwarp();
#pragma unroll
    for (int k = 0; k < 8; k++) r4c[k] = row4col[lane + 32 * k];

    // ---- augmenting row reduction (JV): tighten duals, steal columns.
    unsigned long long dij = 0;
    {
        unsigned long long work = free_rows;
        int budget = 512;
        while (work) {
            int i = __ffsll((long long)work) - 1;
            work &= work - 1;
            bool active = true;
            while (active) {
                if (--budget < 0) { dij |= (1ull << i) | work; work = 0; break; }
                const float* crow = cost + i * CPAD;
                float rq[8];
#pragma unroll
                for (int k = 0; k < 8; k++) rq[k] = crow[lane + 32 * k] - vv[k];

                // lane-local (min m, 2nd-min s) via pairwise merge tree
                float lo01 = fminf(rq[0], rq[1]), hi01 = fmaxf(rq[0], rq[1]);
                float lo23 = fminf(rq[2], rq[3]), hi23 = fmaxf(rq[2], rq[3]);
                float lo45 = fminf(rq[4], rq[5]), hi45 = fmaxf(rq[4], rq[5]);
                float lo67 = fminf(rq[6], rq[7]), hi67 = fmaxf(rq[6], rq[7]);
                float loA = fminf(lo01, lo23);
                float sA  = fminf(fmaxf(lo01, lo23), fminf(hi01, hi23));
                float loB = fminf(lo45, lo67);
                float sB  = fminf(fmaxf(lo45, lo67), fminf(hi45, hi67));
                float m   = fminf(loA, loB);
                float s   = fminf(fmaxf(loA, loB), fminf(sA, sB));

                const unsigned km = f2k(m);
                const unsigned g1 = redux_min_u32(km);
                const float    u1 = k2f(g1);
                const bool     win = (km == g1);

                // 2nd-min redux + ballot overlap the argmin-pack redux below
                const unsigned c2 = win ? f2k(s) : km;
                unsigned pk = 0xFFFFFFFFu;
#pragma unroll
                for (int k = 0; k < 8; k++) {
                    const unsigned c = ((unsigned)(lane + 32 * k) << 9)
                                     | (unsigned)(r4c[k] + 1);
                    pk = min(pk, (rq[k] == u1) ? c : 0xFFFFFFFFu);
                }
                const unsigned g2     = redux_min_u32(c2);
                const unsigned packed = redux_min_u32(pk);
                const unsigned nb = __ballot_sync(FULL, win);
                const float u2 = (__popc(nb) >= 2) ? u1 : k2f(g2);

                const int j1 = (int)(packed >> 9);
                const int k1 = (int)(packed & 511u) - 1;

                if (lane == 0) u[i] = u2;

                if (u1 < u2) {                // take j1 (steal if held)
                    if ((j1 & 31) == lane) { vv[j1 >> 5] -= (u2 - u1); r4c[j1 >> 5] = i; }
                    if (lane == 0) {
                        row4col[j1] = i; col4row[i] = j1;
                        if (k1 >= 0) col4row[k1] = -1;
                    }
                    if (k1 >= 0) i = k1;       // continue with displaced row
                    else         active = false;
                } else {                       // u1 == u2 (>=2 cols at u1)
                    if (k1 < 0) {              // j1 free: take it (slack 0)
                        if ((j1 & 31) == lane) r4c[j1 >> 5] = i;
                        if (lane == 0) { row4col[j1] = i; col4row[i] = j1; }
                        active = false;
                    } else {
                        // j2 = next col with rq == u2, excluding j1 (rare)
                        unsigned pk2 = 0xFFFFFFFFu;
#pragma unroll
                        for (int k = 0; k < 8; k++) {
                            const int q = lane + 32 * k;
                            const unsigned c = ((unsigned)q << 9)
                                             | (unsigned)(r4c[k] + 1);
                            const bool ok = (q != j1) && (rq[k] == u2);
                            pk2 = min(pk2, ok ? c : 0xFFFFFFFFu);
                        }
                        const unsigned packed2 = redux_min_u32(pk2);
                        const int j2  = (int)(packed2 >> 9);
                        const int k2r = (int)(packed2 & 511u) - 1;
                        if (k2r < 0) {         // j2 free: take it (slack 0)
                            if ((j2 & 31) == lane) r4c[j2 >> 5] = i;
                            if (lane == 0) { row4col[j2] = i; col4row[i] = j2; }
                        } else {
                            dij |= 1ull << i;  // defer to Dijkstra
                        }
                        active = false;
                    }
                }
            }
        }
    }
    __syncwarp();

    // ---- exact Dijkstra augmentation for remaining rows
    while (dij) {
        const int cur_row = __ffsll((long long)dij) - 1;
        dij &= dij - 1;

        unsigned scanned = 0;          // bit k -> own column lane+32k in SC
        unsigned long long sr = 0;     // scanned-row set (uniform)
#pragma unroll
        for (int k = 0; k < 8; k++) sh[k] = FINF;

        int   i      = cur_row;
        float minval = 0.0f;
        int   sink;

        while (true) {
            sr |= 1ull << i;
            const float base = minval - u[i];
            const float* crow = cost + i * CPAD;

            float cand[8];
#pragma unroll
            for (int k = 0; k < 8; k++) {
                const int q = lane + 32 * k;
                const bool un = !((scanned >> k) & 1u);
                const float r = (base + crow[q]) - vv[k];
                if (un && r < sh[k]) { sh[k] = r; path[q] = i; }
                cand[k] = un ? sh[k] : FINF;
            }
            float m01 = fminf(cand[0], cand[1]), m23 = fminf(cand[2], cand[3]);
            float m45 = fminf(cand[4], cand[5]), m67 = fminf(cand[6], cand[7]);
            float bv  = fminf(fminf(m01, m23), fminf(m45, m67));
            const unsigned key = f2k(bv);

            unsigned pk = 0xFFFFFFFFu;
#pragma unroll
            for (int k = 0; k < 8; k++) {
                const unsigned c = ((unsigned)(lane + 32 * k) << 9)
                                 | (unsigned)(r4c[k] + 1);
                pk = min(pk, (cand[k] == bv) ? c : 0xFFFFFFFFu);
            }

            const unsigned gkey   = redux_min_u32(key);
            const unsigned pk2    = (key == gkey) ? pk : 0xFFFFFFFFu;
            const unsigned packed = redux_min_u32(pk2);
            minval = k2f(gkey);

            const int j  = (int)(packed >> 9);
            const int r4 = (int)(packed & 511u) - 1;
            if ((j & 31) == lane) scanned |= 1u << (j >> 5);
            if (r4 < 0) { sink = j; break; }
            i = r4;
        }

        // write back shortest for scanned columns (dual u update reads them)
#pragma unroll
        for (int k = 0; k < 8; k++)
            if ((scanned >> k) & 1u) shsh[lane + 32 * k] = sh[k];
        __syncwarp();

        // dual updates
#pragma unroll
        for (int h = 0; h < 2; h++) {
            const int r = lane + 32 * h;
            if (((sr >> r) & 1ull) && r != cur_row) {
                u[r] += minval - shsh[col4row[r]];
            }
        }
        if (lane == 0) u[cur_row] += minval;
#pragma unroll
        for (int k = 0; k < 8; k++) {
            if ((scanned >> k) & 1u) vv[k] -= minval - sh[k];
        }
        __syncwarp();

        // augment along alternating path (serial, lane 0)
        if (lane == 0) {
            int j = sink;
            while (true) {
                int ii = path[j];
                row4col[j] = ii;
                int t = col4row[ii];
                col4row[ii] = j;
                j = t;
                if (ii == cur_row) break;
            }
        }
        __syncwarp();
#pragma unroll
        for (int k = 0; k < 8; k++) r4c[k] = row4col[lane + 32 * k];
    }

    // ---- outputs
    float* out_ind  = out + (size_t)b * QQ;
    float* out_mask = out + (size_t)BB * QQ + (size_t)b * QQ;
#pragma unroll
    for (int k = 0; k < 8; k++) {
        const int q = lane + 32 * k;
        const int r = row4col[q];
        out_ind[q]  = (r >= 0) ? (float)r : 0.0f;
        out_mask[q] = (r >= 0) ? 1.0f : 0.0f;
    }
}

extern "C" void kernel_launch(void* const* d_in, const int* in_sizes, int n_in,
                              void* d_out, int out_size) {
    const float* gious = nullptr;
    const int*   nact  = nullptr;
    for (int i = 0; i < n_in; i++) {
        if (in_sizes[i] == BB * QQ * GG)      gious = (const float*)d_in[i];
        else if (in_sizes[i] == BB)           nact  = (const int*)d_in[i];
    }

    const size_t smem = (size_t)GG * CPAD * sizeof(float)   // cost
                      + (size_t)QQ * sizeof(float)          // shortest mirror
                      + (size_t)GG * sizeof(float)          // u
                      + (size_t)QQ * sizeof(int)            // path
                      + (size_t)QQ * sizeof(int)            // row4col
                      + (size_t)GG * sizeof(int)            // col4row
                      + (size_t)QQ * sizeof(int)            // claim
                      + (size_t)GG * sizeof(int);           // row argmin

    cudaFuncSetAttribute(matcher_lsa_kernel,
                         cudaFuncAttributeMaxDynamicSharedMemorySize, (int)smem);

    matcher_lsa_kernel<<<BB, 32, smem>>>(gious, nact, (float*)d_out);
}